// round 1
// baseline (speedup 1.0000x reference)
#include <cuda_runtime.h>
#include <math.h>

// Problem constants (fixed shapes)
constexpr int S_LEN  = 4096;
constexpr int D_MODEL = 768;
constexpr int NHEADS = 12;
constexpr int DHEAD  = 64;
constexpr int BATCH  = 2;
constexpr int BH     = BATCH * NHEADS;   // 24
constexpr int MROWS  = BATCH * S_LEN;    // 8192

// Scratch for projected Q,K,V in [b,h,s,dk] layout (25.2 MB each)
__device__ float g_Q[(size_t)BH * S_LEN * DHEAD];
__device__ float g_K[(size_t)BH * S_LEN * DHEAD];
__device__ float g_V[(size_t)BH * S_LEN * DHEAD];

// ---------------------------------------------------------------------------
// Projection GEMM:  out = A @ W^T
// A: [8192, 768] row-major, W: [768, 768] row-major ([out,in]) -> NT GEMM,
// both operands are K-contiguous so tiles load symmetrically.
// Output written directly in per-head layout g_X[(b*12+h)*4096 + s][dk].
// grid = (N/64 = 12, M/64 = 128), block = 256 (16x16 threads, 4x4 microtile)
// ---------------------------------------------------------------------------
__global__ __launch_bounds__(256) void proj_kernel(
    const float* __restrict__ A, const float* __restrict__ W, int sel)
{
    __shared__ float As[64][17];
    __shared__ float Bs[64][17];

    float* outp = (sel == 0) ? g_Q : (sel == 1) ? g_K : g_V;

    const int nTile = blockIdx.x;   // == head index (64 cols == one head)
    const int mTile = blockIdx.y;
    const int tid = threadIdx.x;
    const int wy = tid >> 4;        // 0..15
    const int wx = tid & 15;        // 0..15
    const int m0 = wy * 4, n0 = wx * 4;
    const int mBase = mTile * 64, nBase = nTile * 64;

    // loader mapping: row = tid/4 (0..63), 4 consecutive floats at col (tid%4)*4
    const int lr = tid >> 2;
    const int lc = (tid & 3) * 4;

    float acc[4][4] = {};

    for (int k0 = 0; k0 < D_MODEL; k0 += 16) {
        float4 av = *reinterpret_cast<const float4*>(
            &A[(size_t)(mBase + lr) * D_MODEL + k0 + lc]);
        float4 bv = *reinterpret_cast<const float4*>(
            &W[(size_t)(nBase + lr) * D_MODEL + k0 + lc]);
        As[lr][lc + 0] = av.x; As[lr][lc + 1] = av.y;
        As[lr][lc + 2] = av.z; As[lr][lc + 3] = av.w;
        Bs[lr][lc + 0] = bv.x; Bs[lr][lc + 1] = bv.y;
        Bs[lr][lc + 2] = bv.z; Bs[lr][lc + 3] = bv.w;
        __syncthreads();

        #pragma unroll
        for (int kk = 0; kk < 16; kk++) {
            float a[4], b[4];
            #pragma unroll
            for (int ii = 0; ii < 4; ii++) a[ii] = As[m0 + ii][kk];
            #pragma unroll
            for (int jj = 0; jj < 4; jj++) b[jj] = Bs[n0 + jj][kk];
            #pragma unroll
            for (int ii = 0; ii < 4; ii++)
                #pragma unroll
                for (int jj = 0; jj < 4; jj++)
                    acc[ii][jj] = fmaf(a[ii], b[jj], acc[ii][jj]);
        }
        __syncthreads();
    }

    // epilogue: head h = nTile (block n-range == exactly one head)
    #pragma unroll
    for (int ii = 0; ii < 4; ii++) {
        int m = mBase + m0 + ii;
        int b = m / S_LEN, s = m % S_LEN;
        size_t base = (((size_t)(b * NHEADS + nTile) * S_LEN) + s) * DHEAD + n0;
        #pragma unroll
        for (int jj = 0; jj < 4; jj++) outp[base + jj] = acc[ii][jj];
    }
}

// ---------------------------------------------------------------------------
// Flash attention (causal, diagonal=0), fp32, online softmax.
// grid = (S/64 = 64 qtiles, BH = 24), block = 256 (16x16, 4x4 microtile)
// Dynamic smem: Qs[64][65] + Ks[64][65] + Ps[64][65] + Vs[64][64]
// ---------------------------------------------------------------------------
constexpr int QS_OFF = 0;
constexpr int KS_OFF = 64 * 65;
constexpr int PS_OFF = 2 * 64 * 65;
constexpr int VS_OFF = 3 * 64 * 65;
constexpr int SMEM_ATTN_FLOATS = 3 * 64 * 65 + 64 * 64;   // 16576
constexpr int SMEM_ATTN_BYTES  = SMEM_ATTN_FLOATS * 4;     // 66304

__global__ __launch_bounds__(256) void attn_kernel(float* __restrict__ out)
{
    extern __shared__ float sm[];
    float (*Qs)[65] = reinterpret_cast<float(*)[65]>(sm + QS_OFF);
    float (*Ks)[65] = reinterpret_cast<float(*)[65]>(sm + KS_OFF);
    float (*Ps)[65] = reinterpret_cast<float(*)[65]>(sm + PS_OFF);
    float (*Vs)[64] = reinterpret_cast<float(*)[64]>(sm + VS_OFF);

    const int bh = blockIdx.y;
    const int qTile = blockIdx.x;
    const int q0 = qTile * 64;
    const int tid = threadIdx.x;
    const int wy = tid >> 4, wx = tid & 15;
    const int i0 = wy * 4, j0 = wx * 4;   // j0 doubles as d0 in the PV stage

    const float* __restrict__ Qp = g_Q + (size_t)bh * S_LEN * DHEAD;
    const float* __restrict__ Kp = g_K + (size_t)bh * S_LEN * DHEAD;
    const float* __restrict__ Vp = g_V + (size_t)bh * S_LEN * DHEAD;

    const float scale = 0.125f;  // 1/sqrt(64)

    // loader mapping: row = tid/4 (0..63), one float4 at col4 base (tid%4)*4
    const int lr = tid >> 2;
    const int lc4 = (tid & 3) * 4;   // float4 index *4 -> starting col of 16-col strip

    // Load + scale Q tile (each thread: 4 float4 = 16 floats of one row)
    {
        #pragma unroll
        for (int u = 0; u < 4; u++) {
            float4 v = *reinterpret_cast<const float4*>(
                &Qp[(size_t)(q0 + lr) * DHEAD + (lc4 + u) * 4]);
            Qs[lr][(lc4 + u) * 4 + 0] = v.x * scale;
            Qs[lr][(lc4 + u) * 4 + 1] = v.y * scale;
            Qs[lr][(lc4 + u) * 4 + 2] = v.z * scale;
            Qs[lr][(lc4 + u) * 4 + 3] = v.w * scale;
        }
    }

    float o[4][4] = {};
    float m_i[4], l_i[4];
    #pragma unroll
    for (int ii = 0; ii < 4; ii++) { m_i[ii] = -INFINITY; l_i[ii] = 0.f; }

    for (int jt = 0; jt <= qTile; jt++) {
        __syncthreads();   // Q ready (first iter) / prev PV reads of Ps,Vs done

        // Load K (scalar stores, stride 65) and V (float4 stores, stride 64)
        const int kr0 = jt * 64;
        #pragma unroll
        for (int u = 0; u < 4; u++) {
            float4 kv = *reinterpret_cast<const float4*>(
                &Kp[(size_t)(kr0 + lr) * DHEAD + (lc4 + u) * 4]);
            Ks[lr][(lc4 + u) * 4 + 0] = kv.x;
            Ks[lr][(lc4 + u) * 4 + 1] = kv.y;
            Ks[lr][(lc4 + u) * 4 + 2] = kv.z;
            Ks[lr][(lc4 + u) * 4 + 3] = kv.w;
            float4 vv = *reinterpret_cast<const float4*>(
                &Vp[(size_t)(kr0 + lr) * DHEAD + (lc4 + u) * 4]);
            *reinterpret_cast<float4*>(&Vs[lr][(lc4 + u) * 4]) = vv;
        }
        __syncthreads();

        // S = (Q*scale) @ K^T for this 64x64 tile
        float sv[4][4] = {};
        #pragma unroll 8
        for (int kk = 0; kk < DHEAD; kk++) {
            float a[4], b[4];
            #pragma unroll
            for (int ii = 0; ii < 4; ii++) a[ii] = Qs[i0 + ii][kk];
            #pragma unroll
            for (int jj = 0; jj < 4; jj++) b[jj] = Ks[j0 + jj][kk];
            #pragma unroll
            for (int ii = 0; ii < 4; ii++)
                #pragma unroll
                for (int jj = 0; jj < 4; jj++)
                    sv[ii][jj] = fmaf(a[ii], b[jj], sv[ii][jj]);
        }

        // Causal mask only on the diagonal tile (col > row -> -inf)
        if (jt == qTile) {
            #pragma unroll
            for (int ii = 0; ii < 4; ii++)
                #pragma unroll
                for (int jj = 0; jj < 4; jj++)
                    if (j0 + jj > i0 + ii) sv[ii][jj] = -INFINITY;
        }

        // Online softmax: per-row reduce over the 16-lane row group (width 16)
        #pragma unroll
        for (int ii = 0; ii < 4; ii++) {
            float rm = fmaxf(fmaxf(sv[ii][0], sv[ii][1]),
                             fmaxf(sv[ii][2], sv[ii][3]));
            #pragma unroll
            for (int off = 8; off; off >>= 1)
                rm = fmaxf(rm, __shfl_xor_sync(0xffffffffu, rm, off, 16));

            float newm = fmaxf(m_i[ii], rm);
            float corr = __expf(m_i[ii] - newm);   // 0 on first tile (m=-inf)
            m_i[ii] = newm;

            float rs = 0.f;
            #pragma unroll
            for (int jj = 0; jj < 4; jj++) {
                float p = __expf(sv[ii][jj] - newm);
                sv[ii][jj] = p;
                rs += p;
            }
            #pragma unroll
            for (int off = 8; off; off >>= 1)
                rs += __shfl_xor_sync(0xffffffffu, rs, off, 16);

            l_i[ii] = l_i[ii] * corr + rs;
            #pragma unroll
            for (int dd = 0; dd < 4; dd++) o[ii][dd] *= corr;
        }

        // Stage P for the PV GEMM
        #pragma unroll
        for (int ii = 0; ii < 4; ii++)
            #pragma unroll
            for (int jj = 0; jj < 4; jj++)
                Ps[i0 + ii][j0 + jj] = sv[ii][jj];
        __syncthreads();

        // O += P @ V  (d0 = j0 for this thread)
        #pragma unroll 8
        for (int j = 0; j < 64; j++) {
            float a[4], b[4];
            #pragma unroll
            for (int ii = 0; ii < 4; ii++) a[ii] = Ps[i0 + ii][j];
            #pragma unroll
            for (int dd = 0; dd < 4; dd++) b[dd] = Vs[j][j0 + dd];
            #pragma unroll
            for (int ii = 0; ii < 4; ii++)
                #pragma unroll
                for (int dd = 0; dd < 4; dd++)
                    o[ii][dd] = fmaf(a[ii], b[dd], o[ii][dd]);
        }
    }

    // Write merged-head output: out[b][s][h*64 + d]
    const int b = bh / NHEADS, h = bh % NHEADS;
    #pragma unroll
    for (int ii = 0; ii < 4; ii++) {
        int row = q0 + i0 + ii;
        float inv = 1.f / l_i[ii];
        size_t base = ((size_t)b * S_LEN + row) * D_MODEL + h * DHEAD + j0;
        #pragma unroll
        for (int dd = 0; dd < 4; dd++) out[base + dd] = o[ii][dd] * inv;
    }
}

// ---------------------------------------------------------------------------
extern "C" void kernel_launch(void* const* d_in, const int* in_sizes, int n_in,
                              void* d_out, int out_size)
{
    const float* x  = (const float*)d_in[0];
    const float* Wq = (const float*)d_in[1];
    const float* Wk = (const float*)d_in[2];
    const float* Wv = (const float*)d_in[3];
    float* out = (float*)d_out;

    static bool attr_set = false;  // idempotent attribute, safe across replays
    if (!attr_set) {
        cudaFuncSetAttribute(attn_kernel,
                             cudaFuncAttributeMaxDynamicSharedMemorySize,
                             SMEM_ATTN_BYTES);
        attr_set = true;
    }

    dim3 pgrid(D_MODEL / 64, MROWS / 64);   // (12, 128)
    proj_kernel<<<pgrid, 256>>>(x, Wq, 0);
    proj_kernel<<<pgrid, 256>>>(x, Wk, 1);
    proj_kernel<<<pgrid, 256>>>(x, Wv, 2);

    dim3 agrid(S_LEN / 64, BH);             // (64, 24)
    attn_kernel<<<agrid, 256, SMEM_ATTN_BYTES>>>(out);
}